// round 1
// baseline (speedup 1.0000x reference)
#include <cuda_runtime.h>
#include <math.h>

#define NB 2
#define LQ 2048
#define SK 2048
#define HH 8
#define DD 64
#define NHLD (NB*HH*LQ*DD)   // 2,097,152

// Scratch: phi(Q)*qmask laid out [n][h][l][d], phi(K)*kvmask [n][h][s][d], Ksum [n][h][d]
__device__ float g_phiQ[NHLD];
__device__ float g_phiK[NHLD];
__device__ float g_ksum[NB*HH*DD];

// ---------------------------------------------------------------------------
// Kernel A: feature map + mask, with layout transform [n,l,h,d] -> [n,h,l,d]
// ---------------------------------------------------------------------------
__global__ __launch_bounds__(256) void prep_kernel(
    const float* __restrict__ q, const float* __restrict__ k,
    const float* __restrict__ qm, const float* __restrict__ km)
{
    int idx = blockIdx.x * 256 + threadIdx.x;
    if (idx >= NHLD) return;
    int d = idx & 63;
    int l = (idx >> 6) & 2047;
    int h = (idx >> 17) & 7;
    int n = idx >> 20;
    int src = (((n * 2048 + l) * 8 + h) << 6) + d;

    float x = q[src];
    float phq = (x > 0.f) ? (x + 1.f) : expf(x);
    g_phiQ[idx] = phq * qm[n * 2048 + l];

    float y = k[src];
    float phk = (y > 0.f) ? (y + 1.f) : expf(y);
    g_phiK[idx] = phk * km[n * 2048 + l];
}

// ---------------------------------------------------------------------------
// Kernel B: Ksum[n,h,d] = sum_s phiK[n,h,s,d]
// ---------------------------------------------------------------------------
__global__ __launch_bounds__(256) void ksum_kernel()
{
    int nh = blockIdx.x;          // 0..15
    int tid = threadIdx.x;
    int d = tid & 63;
    int g = tid >> 6;             // 0..3
    const float* base = g_phiK + nh * (SK * DD);
    float s = 0.f;
    for (int ss = g; ss < SK; ss += 4)
        s += base[ss * 64 + d];
    __shared__ float red[256];
    red[tid] = s;
    __syncthreads();
    if (tid < 64)
        g_ksum[nh * 64 + tid] = red[tid] + red[tid + 64] + red[tid + 128] + red[tid + 192];
}

// ---------------------------------------------------------------------------
// Kernel C: max-reduction GEMM + gate + output
// grid = (L/64, N*H), block = 256 (16x16), 4x4 microtile, tiles 64x64, K=64
// ---------------------------------------------------------------------------
__global__ __launch_bounds__(256) void attn_main_kernel(
    const float* __restrict__ queries,
    const float* __restrict__ qmask,
    const float* __restrict__ W,
    const float* __restrict__ bias,
    float* __restrict__ out)
{
    __shared__ float Qs[64][68];      // [d][l], stride 68 keeps float4 alignment
    __shared__ float Ks[64][68];      // [d][s]
    __shared__ float redm[64][17];
    __shared__ float ksum_s[64];
    __shared__ float gate_s[64];

    const int tid = threadIdx.x;
    const int tx = tid & 15;          // s sub-block
    const int ty = tid >> 4;          // l sub-block
    const int nh = blockIdx.y;        // n*H + h
    const int l0 = blockIdx.x * 64;

    const float* phiQ = g_phiQ + (nh * LQ + l0) * DD;
    const float* phiK = g_phiK + nh * (SK * DD);

    // --- Load Q tile transposed into Qs[d][l] ---
    {
        int r = tid >> 2;             // row (l) 0..63
        int c = tid & 3;              // d chunk 0..3 (16 d each)
        const float4* src = (const float4*)(phiQ + r * 64 + c * 16);
        #pragma unroll
        for (int k4 = 0; k4 < 4; k4++) {
            float4 v = src[k4];
            int d = c * 16 + k4 * 4;
            Qs[d + 0][r] = v.x; Qs[d + 1][r] = v.y;
            Qs[d + 2][r] = v.z; Qs[d + 3][r] = v.w;
        }
    }
    if (tid < 64) ksum_s[tid] = g_ksum[nh * 64 + tid];

    float m[4] = {-1e30f, -1e30f, -1e30f, -1e30f};

    const int r = tid >> 2;
    const int c = tid & 3;

    for (int s0 = 0; s0 < SK; s0 += 64) {
        // prefetch K tile (LDG before sync to overlap with prior compute tail)
        const float4* src = (const float4*)(phiK + (s0 + r) * 64 + c * 16);
        float4 v0 = src[0], v1 = src[1], v2 = src[2], v3 = src[3];
        __syncthreads();   // previous iteration finished reading Ks
        {
            int d = c * 16;
            Ks[d + 0][r] = v0.x; Ks[d + 1][r] = v0.y; Ks[d + 2][r] = v0.z; Ks[d + 3][r] = v0.w;
            Ks[d + 4][r] = v1.x; Ks[d + 5][r] = v1.y; Ks[d + 6][r] = v1.z; Ks[d + 7][r] = v1.w;
            Ks[d + 8][r] = v2.x; Ks[d + 9][r] = v2.y; Ks[d +10][r] = v2.z; Ks[d +11][r] = v2.w;
            Ks[d +12][r] = v3.x; Ks[d +13][r] = v3.y; Ks[d +14][r] = v3.z; Ks[d +15][r] = v3.w;
        }
        __syncthreads();

        float acc[4][4];
        #pragma unroll
        for (int i = 0; i < 4; i++)
            #pragma unroll
            for (int j = 0; j < 4; j++)
                acc[i][j] = 0.f;

        #pragma unroll 16
        for (int d = 0; d < 64; d++) {
            float4 qv = *(const float4*)&Qs[d][ty * 4];
            float4 kv = *(const float4*)&Ks[d][tx * 4];
            acc[0][0] += qv.x * kv.x; acc[0][1] += qv.x * kv.y;
            acc[0][2] += qv.x * kv.z; acc[0][3] += qv.x * kv.w;
            acc[1][0] += qv.y * kv.x; acc[1][1] += qv.y * kv.y;
            acc[1][2] += qv.y * kv.z; acc[1][3] += qv.y * kv.w;
            acc[2][0] += qv.z * kv.x; acc[2][1] += qv.z * kv.y;
            acc[2][2] += qv.z * kv.z; acc[2][3] += qv.z * kv.w;
            acc[3][0] += qv.w * kv.x; acc[3][1] += qv.w * kv.y;
            acc[3][2] += qv.w * kv.z; acc[3][3] += qv.w * kv.w;
        }
        #pragma unroll
        for (int i = 0; i < 4; i++) {
            float t0 = fmaxf(acc[i][0], acc[i][1]);
            float t1 = fmaxf(acc[i][2], acc[i][3]);
            m[i] = fmaxf(m[i], fmaxf(t0, t1));
        }
    }

    // --- cross-thread max reduce (over tx) ---
    #pragma unroll
    for (int i = 0; i < 4; i++)
        redm[ty * 4 + i][tx] = m[i];
    __syncthreads();

    if (tid < 64) {
        float mx = redm[tid][0];
        #pragma unroll
        for (int j = 1; j < 16; j++) mx = fmaxf(mx, redm[tid][j]);
        // mean via Ksum trick (Qs still holds phiQ tile, [d][l])
        float mean = 0.f;
        #pragma unroll 16
        for (int d = 0; d < 64; d++) mean += Qs[d][tid] * ksum_s[d];
        mean *= (1.0f / (float)SK);
        float lg = fmaf(mean, W[0], fmaf(mx, W[1], bias[0]));
        gate_s[tid] = 1.0f / (1.0f + expf(-lg));
    }
    __syncthreads();

    // --- output: queries * q_mask * gate, layout [n,l,h,d] ---
    const int n = nh >> 3;
    const int h = nh & 7;
    const float* qsrc = queries + ((((size_t)n * LQ + l0) * HH + h) << 6);
    float* dst = out + ((((size_t)n * LQ + l0) * HH + h) << 6);
    #pragma unroll 4
    for (int e = tid; e < 64 * 64; e += 256) {
        int l = e >> 6;
        int d = e & 63;
        int off = l * (HH * DD) + d;
        dst[off] = qsrc[off] * qmask[n * LQ + l0 + l] * gate_s[l];
    }
}

// ---------------------------------------------------------------------------
extern "C" void kernel_launch(void* const* d_in, const int* in_sizes, int n_in,
                              void* d_out, int out_size)
{
    const float* queries = (const float*)d_in[0];
    const float* keys    = (const float*)d_in[1];
    // d_in[2] = values (unused by reference output)
    const float* q_mask  = (const float*)d_in[3];
    const float* kv_mask = (const float*)d_in[4];
    const float* W       = (const float*)d_in[5];
    const float* b       = (const float*)d_in[6];
    float* out = (float*)d_out;

    prep_kernel<<<NHLD / 256, 256>>>(queries, keys, q_mask, kv_mask);
    ksum_kernel<<<NB * HH, 256>>>();
    dim3 grid(LQ / 64, NB * HH);
    attn_main_kernel<<<grid, 256>>>(queries, q_mask, W, b, out);
}

// round 3
// speedup vs baseline: 3.2460x; 3.2460x over previous
#include <cuda_runtime.h>
#include <cuda_bf16.h>
#include <math.h>
#include <stdint.h>

#define NB 2
#define LQ 2048
#define SK 2048
#define HH 8
#define DD 64
#define NHT (NB*HH)
#define NHLD (NB*HH*LQ*DD)   // 2,097,152

// Scratch (layout [n][h][row][d]), 256B-aligned for vector/cp.async access
__device__ __align__(256) __nv_bfloat16 g_Qhi[NHLD];
__device__ __align__(256) __nv_bfloat16 g_Qlo[NHLD];
__device__ __align__(256) __nv_bfloat16 g_Khi[NHLD];
__device__ __align__(256) __nv_bfloat16 g_Klo[NHLD];
__device__ __align__(256) float g_ksum[NHT*DD];

// ---------------------------------------------------------------------------
// PTX helpers (portable ISA only: ldmatrix / mma.sync / cp.async, sm_80+)
// ---------------------------------------------------------------------------
__device__ __forceinline__ uint32_t smem_u32_of(const void* p) {
    uint32_t a;
    asm("{ .reg .u64 t; cvta.to.shared.u64 t, %1; cvt.u32.u64 %0, t; }" : "=r"(a) : "l"(p));
    return a;
}
#define LDM4(r, addr) \
    asm volatile("ldmatrix.sync.aligned.m8n8.x4.shared.b16 {%0,%1,%2,%3}, [%4];" \
        : "=r"((r)[0]), "=r"((r)[1]), "=r"((r)[2]), "=r"((r)[3]) : "r"(addr))
#define MMA16816(c, a, b) \
    asm volatile("mma.sync.aligned.m16n8k16.row.col.f32.bf16.bf16.f32 " \
        "{%0,%1,%2,%3}, {%4,%5,%6,%7}, {%8,%9}, {%0,%1,%2,%3};" \
        : "+f"((c)[0]), "+f"((c)[1]), "+f"((c)[2]), "+f"((c)[3]) \
        : "r"((a)[0]), "r"((a)[1]), "r"((a)[2]), "r"((a)[3]), "r"((b)[0]), "r"((b)[1]))
#define CPA16(s, g) \
    asm volatile("cp.async.cg.shared.global [%0], [%1], 16;" :: "r"(s), "l"(g))
#define CPC()  asm volatile("cp.async.commit_group;" ::: "memory")
#define CPW1() asm volatile("cp.async.wait_group 1;" ::: "memory")
#define CPW0() asm volatile("cp.async.wait_group 0;" ::: "memory")

// SMEM byte offsets (dynamic smem)
#define A_HI_OFF 0
#define A_LO_OFF 16384
#define B_OFF    32768            // + buf*32768 ; hi at +0, lo at +16384
#define RMAX_OFF 98304            // float[128][2]
#define KS_OFF   99328            // float[64]
#define SMEM_TOTAL 99584

// ---------------------------------------------------------------------------
// Kernel A: feature map + mask + [n,l,h,d]->[n,h,l,d] + bf16 hi/lo split
// One thread per d-pair; bf16x2 packed stores.
// ---------------------------------------------------------------------------
__global__ __launch_bounds__(256) void prep_kernel(
    const float* __restrict__ q, const float* __restrict__ k,
    const float* __restrict__ qm, const float* __restrict__ km)
{
    int idx = blockIdx.x * 256 + threadIdx.x;      // pair index, [0, NHLD/2)
    int dp = idx & 31;
    int l  = (idx >> 5) & 2047;
    int h  = (idx >> 16) & 7;
    int n  = idx >> 19;
    int srcp = (((n * 2048 + l) * 8 + h) << 5) + dp;

    float2 qv = ((const float2*)q)[srcp];
    float2 kv = ((const float2*)k)[srcp];
    float qmv = qm[n * 2048 + l];
    float kmv = km[n * 2048 + l];

    float phqx = ((qv.x > 0.f) ? (qv.x + 1.f) : expf(qv.x)) * qmv;
    float phqy = ((qv.y > 0.f) ? (qv.y + 1.f) : expf(qv.y)) * qmv;
    float phkx = ((kv.x > 0.f) ? (kv.x + 1.f) : expf(kv.x)) * kmv;
    float phky = ((kv.y > 0.f) ? (kv.y + 1.f) : expf(kv.y)) * kmv;

    __nv_bfloat16 qhx = __float2bfloat16(phqx), qhy = __float2bfloat16(phqy);
    __nv_bfloat16 khx = __float2bfloat16(phkx), khy = __float2bfloat16(phky);
    __nv_bfloat162 qh2; qh2.x = qhx; qh2.y = qhy;
    __nv_bfloat162 kh2; kh2.x = khx; kh2.y = khy;
    __nv_bfloat162 ql2; ql2.x = __float2bfloat16(phqx - __bfloat162float(qhx));
                        ql2.y = __float2bfloat16(phqy - __bfloat162float(qhy));
    __nv_bfloat162 kl2; kl2.x = __float2bfloat16(phkx - __bfloat162float(khx));
                        kl2.y = __float2bfloat16(phky - __bfloat162float(khy));

    ((__nv_bfloat162*)g_Qhi)[idx] = qh2;
    ((__nv_bfloat162*)g_Qlo)[idx] = ql2;
    ((__nv_bfloat162*)g_Khi)[idx] = kh2;
    ((__nv_bfloat162*)g_Klo)[idx] = kl2;
}

// ---------------------------------------------------------------------------
// Kernel B: Ksum[n,h,d] = sum_s (Khi+Klo)[n,h,s,d]
// ---------------------------------------------------------------------------
__global__ __launch_bounds__(256) void ksum_kernel()
{
    int nh = blockIdx.x;
    int tid = threadIdx.x;
    int dp = tid & 31;          // d-pair
    int g  = tid >> 5;          // 0..7
    const uint32_t* bh = (const uint32_t*)(g_Khi + (size_t)nh * SK * DD);
    const uint32_t* bl = (const uint32_t*)(g_Klo + (size_t)nh * SK * DD);
    float s0 = 0.f, s1 = 0.f;
    for (int ss = g; ss < SK; ss += 8) {
        uint32_t vh = bh[ss * 32 + dp];
        uint32_t vl = bl[ss * 32 + dp];
        float2 fh = __bfloat1622float2(*(__nv_bfloat162*)&vh);
        float2 fl = __bfloat1622float2(*(__nv_bfloat162*)&vl);
        s0 += fh.x + fl.x;
        s1 += fh.y + fl.y;
    }
    __shared__ float r0[256], r1[256];
    r0[tid] = s0; r1[tid] = s1;
    __syncthreads();
    if (tid < 32) {
        float a0 = 0.f, a1 = 0.f;
        #pragma unroll
        for (int j = 0; j < 8; j++) { a0 += r0[tid + j * 32]; a1 += r1[tid + j * 32]; }
        g_ksum[nh * 64 + tid * 2]     = a0;
        g_ksum[nh * 64 + tid * 2 + 1] = a1;
    }
}

// ---------------------------------------------------------------------------
// Kernel C: HMMA score GEMM (bf16 hi/lo, 3 accumulation passes) + row-max
//           + gate + output.  grid=(L/128, N*H), block=256 (8 warps, 4x2).
// ---------------------------------------------------------------------------
__global__ void __launch_bounds__(256) attn_mma_kernel(
    const float* __restrict__ queries,
    const float* __restrict__ qmask,
    const float* __restrict__ W,
    const float* __restrict__ bias,
    float* __restrict__ out)
{
    extern __shared__ char sm[];
    const uint32_t smu = smem_u32_of(sm);
    float* rowmax = (float*)(sm + RMAX_OFF);
    float* ksum_s = (float*)(sm + KS_OFF);

    const int tid  = threadIdx.x;
    const int lane = tid & 31;
    const int wid  = tid >> 5;
    const int wx   = wid & 1;       // n-block (64 cols each)
    const int wy   = wid >> 1;      // m-block (32 rows each)
    const int nh   = blockIdx.y;
    const int l0   = blockIdx.x * 128;

    // --- A tiles (Q hi/lo) : LDG + swizzled STS, resident all kernel ---
    {
        const char* qh = (const char*)(g_Qhi + ((size_t)nh * LQ + l0) * DD);
        const char* ql = (const char*)(g_Qlo + ((size_t)nh * LQ + l0) * DD);
        #pragma unroll
        for (int c = tid; c < 1024; c += 256) {
            int row = c >> 3, dc = c & 7;
            uint32_t dst = row * 128 + ((dc ^ (row & 7)) << 4);
            *(uint4*)(sm + A_HI_OFF + dst) = *(const uint4*)(qh + c * 16);
            *(uint4*)(sm + A_LO_OFF + dst) = *(const uint4*)(ql + c * 16);
        }
    }
    if (tid < 64) ksum_s[tid] = g_ksum[nh * 64 + tid];

    // ldmatrix lane->address precompute
    const int mat   = lane >> 3;
    const int rin   = lane & 7;
    const int a_row = wy * 32 + (mat & 1) * 8 + rin;     // + i*16
    const int a_kc  = mat >> 1;                          // + 2*kstep
    const int b_roff = wx * 64 + (mat >> 1) * 8 + rin;   // + jp*16
    const int b_kc  = mat & 1;                           // + 2*kstep

    const char* khi_base = (const char*)(g_Khi + (size_t)nh * SK * DD);
    const char* klo_base = (const char*)(g_Klo + (size_t)nh * SK * DD);

    // issue cp.async for K tile t into buffer b
    auto issue_b = [&](int buf, int t) {
        uint32_t bu = smu + B_OFF + buf * 32768;
        const char* gh = khi_base + (size_t)t * 128 * DD * 2;
        const char* gl = klo_base + (size_t)t * 128 * DD * 2;
        #pragma unroll
        for (int kk = 0; kk < 4; kk++) {
            int c = tid + kk * 256;
            int row = c >> 3, dc = c & 7;
            uint32_t sw = row * 128 + ((dc ^ (row & 7)) << 4);
            CPA16(bu + sw, gh + c * 16);
            CPA16(bu + 16384 + sw, gl + c * 16);
        }
    };

    issue_b(0, 0); CPC();

    float mA[2] = {-1e30f, -1e30f};
    float mB[2] = {-1e30f, -1e30f};

    for (int t = 0; t < 16; t++) {
        if (t < 15) { issue_b((t + 1) & 1, t + 1); CPC(); CPW1(); }
        else        { CPW0(); }
        __syncthreads();

        const uint32_t Bu = smu + B_OFF + (t & 1) * 32768;
        float acc[2][8][4];
        #pragma unroll
        for (int i = 0; i < 2; i++)
            #pragma unroll
            for (int j = 0; j < 8; j++)
                acc[i][j][0] = acc[i][j][1] = acc[i][j][2] = acc[i][j][3] = 0.f;

        #pragma unroll
        for (int ks = 0; ks < 4; ks++) {
            const int kb = ks * 2;
            uint32_t ah[2][4], al[2][4];
            #pragma unroll
            for (int i = 0; i < 2; i++) {
                int ar = a_row + 16 * i;
                uint32_t ad = smu + ar * 128 + (((a_kc + kb) ^ (ar & 7)) << 4);
                LDM4(ah[i], ad + A_HI_OFF);
                LDM4(al[i], ad + A_LO_OFF);
            }
            uint32_t bh[8][2], bl[8][2];
            #pragma unroll
            for (int jp = 0; jp < 4; jp++) {
                int br = b_roff + jp * 16;
                uint32_t bd = Bu + br * 128 + (((b_kc + kb) ^ (br & 7)) << 4);
                uint32_t r[4];
                LDM4(r, bd);
                bh[jp*2][0] = r[0]; bh[jp*2][1] = r[1];
                bh[jp*2+1][0] = r[2]; bh[jp*2+1][1] = r[3];
                LDM4(r, bd + 16384);
                bl[jp*2][0] = r[0]; bl[jp*2][1] = r[1];
                bl[jp*2+1][0] = r[2]; bl[jp*2+1][1] = r[3];
            }
            #pragma unroll
            for (int i = 0; i < 2; i++)
                #pragma unroll
                for (int j = 0; j < 8; j++) {
                    MMA16816(acc[i][j], ah[i], bh[j]);   // hi*hi
                    MMA16816(acc[i][j], ah[i], bl[j]);   // hi*lo
                    MMA16816(acc[i][j], al[i], bh[j]);   // lo*hi
                }
        }

        #pragma unroll
        for (int i = 0; i < 2; i++)
            #pragma unroll
            for (int j = 0; j < 8; j++) {
                mA[i] = fmaxf(mA[i], fmaxf(acc[i][j][0], acc[i][j][1]));
                mB[i] = fmaxf(mB[i], fmaxf(acc[i][j][2], acc[i][j][3]));
            }
        __syncthreads();   // all warps done with this B buffer
    }

    // --- reduce max across lane%4 (same rows), write per-row per-wx ---
    #pragma unroll
    for (int off = 1; off <= 2; off <<= 1) {
        #pragma unroll
        for (int i = 0; i < 2; i++) {
            mA[i] = fmaxf(mA[i], __shfl_xor_sync(0xffffffff, mA[i], off));
            mB[i] = fmaxf(mB[i], __shfl_xor_sync(0xffffffff, mB[i], off));
        }
    }
    if ((lane & 3) == 0) {
        int r = lane >> 2;
        #pragma unroll
        for (int i = 0; i < 2; i++) {
            rowmax[(wy * 32 + i * 16 + r) * 2 + wx]     = mA[i];
            rowmax[(wy * 32 + i * 16 + r + 8) * 2 + wx] = mB[i];
        }
    }
    __syncthreads();

    // --- epilogue: thread tid<128 owns row l0+tid ---
    if (tid < 128) {
        const int l = l0 + tid;
        const int n = nh >> 3;
        const int h = nh & 7;
        float mx = fmaxf(rowmax[tid * 2], rowmax[tid * 2 + 1]);

        // mean via Ksum trick; phiQ reconstructed from smem A hi+lo
        float mean = 0.f;
        const int swl = tid & 7;
        #pragma unroll
        for (int dc = 0; dc < 8; dc++) {
            uint32_t off = tid * 128 + ((dc ^ swl) << 4);
            uint4 vh = *(const uint4*)(sm + A_HI_OFF + off);
            uint4 vl = *(const uint4*)(sm + A_LO_OFF + off);
            const uint32_t* ph = (const uint32_t*)&vh;
            const uint32_t* pl = (const uint32_t*)&vl;
            #pragma unroll
            for (int w = 0; w < 4; w++) {
                float2 fh = __bfloat1622float2(*(__nv_bfloat162*)&ph[w]);
                float2 fl = __bfloat1622float2(*(__nv_bfloat162*)&pl[w]);
                mean += (fh.x + fl.x) * ksum_s[dc * 8 + w * 2];
                mean += (fh.y + fl.y) * ksum_s[dc * 8 + w * 2 + 1];
            }
        }
        mean *= (1.0f / (float)SK);

        float lg = fmaf(mean, W[0], fmaf(mx, W[1], bias[0]));
        float gate = 1.0f / (1.0f + expf(-lg));
        float s = gate * qmask[n * LQ + l];

        size_t obase = ((((size_t)n * LQ + l) * HH + h) << 6);
        const float4* qs = (const float4*)(queries + obase);
        float4* dst = (float4*)(out + obase);
        #pragma unroll
        for (int j = 0; j < 16; j++) {
            float4 v = qs[j];
            v.x *= s; v.y *= s; v.z *= s; v.w *= s;
            dst[j] = v;
        }
    }
}

// ---------------------------------------------------------------------------
extern "C" void kernel_launch(void* const* d_in, const int* in_sizes, int n_in,
                              void* d_out, int out_size)
{
    const float* queries = (const float*)d_in[0];
    const float* keys    = (const float*)d_in[1];
    const float* q_mask  = (const float*)d_in[3];
    const float* kv_mask = (const float*)d_in[4];
    const float* W       = (const float*)d_in[5];
    const float* b       = (const float*)d_in[6];
    float* out = (float*)d_out;

    prep_kernel<<<(NHLD / 2) / 256, 256>>>(queries, keys, q_mask, kv_mask);
    ksum_kernel<<<NHT, 256>>>();

    cudaFuncSetAttribute(attn_mma_kernel,
                         cudaFuncAttributeMaxDynamicSharedMemorySize, SMEM_TOTAL);
    dim3 grid(LQ / 128, NHT);
    attn_mma_kernel<<<grid, 256, SMEM_TOTAL>>>(queries, q_mask, W, b, out);
}

// round 4
// speedup vs baseline: 3.6753x; 1.1323x over previous
#include <cuda_runtime.h>
#include <cuda_bf16.h>
#include <math.h>
#include <stdint.h>

#define NB 2
#define LQ 2048
#define SK 2048
#define HH 8
#define DD 64
#define NHT (NB*HH)
#define NHLD (NB*HH*LQ*DD)   // 2,097,152

// Scratch (layout [n][h][row][d])
__device__ __align__(256) __nv_bfloat16 g_Qhi[NHLD];
__device__ __align__(256) __nv_bfloat16 g_Qlo[NHLD];
__device__ __align__(256) __nv_bfloat16 g_Khi[NHLD];
__device__ __align__(256) __nv_bfloat16 g_Klo[NHLD];
__device__ __align__(256) float g_kpart[NHT*8*DD];
__device__ __align__(256) float g_ksum[NHT*DD];

// ---------------------------------------------------------------------------
// PTX helpers (portable ISA: ldmatrix / mma.sync / cp.async)
// ---------------------------------------------------------------------------
__device__ __forceinline__ uint32_t smem_u32_of(const void* p) {
    uint32_t a;
    asm("{ .reg .u64 t; cvta.to.shared.u64 t, %1; cvt.u32.u64 %0, t; }" : "=r"(a) : "l"(p));
    return a;
}
#define LDM4(r, addr) \
    asm volatile("ldmatrix.sync.aligned.m8n8.x4.shared.b16 {%0,%1,%2,%3}, [%4];" \
        : "=r"((r)[0]), "=r"((r)[1]), "=r"((r)[2]), "=r"((r)[3]) : "r"(addr))
#define MMA16816(c, a0, a1, a2, a3, b0, b1) \
    asm volatile("mma.sync.aligned.m16n8k16.row.col.f32.bf16.bf16.f32 " \
        "{%0,%1,%2,%3}, {%4,%5,%6,%7}, {%8,%9}, {%0,%1,%2,%3};" \
        : "+f"((c)[0]), "+f"((c)[1]), "+f"((c)[2]), "+f"((c)[3]) \
        : "r"(a0), "r"(a1), "r"(a2), "r"(a3), "r"(b0), "r"(b1))
#define CPA16(s, g) \
    asm volatile("cp.async.cg.shared.global [%0], [%1], 16;" :: "r"(s), "l"(g))
#define CPC()  asm volatile("cp.async.commit_group;" ::: "memory")
#define CPW1() asm volatile("cp.async.wait_group 1;" ::: "memory")
#define CPW0() asm volatile("cp.async.wait_group 0;" ::: "memory")

// SMEM byte offsets (dynamic smem)
#define A_HI_OFF 0
#define A_LO_OFF 16384
#define B_OFF    32768            // + buf*32768 ; hi at +0, lo at +16384
#define RMAX_OFF 98304            // float[128][2]
#define KS_OFF   99328            // float[64]
#define GATE_OFF 99584            // float[128]
#define SMEM_TOTAL 100096

// ---------------------------------------------------------------------------
// Kernel A: feature map + mask + [n,l,h,d]->[n,h,l,d] + bf16 hi/lo split
// ---------------------------------------------------------------------------
__global__ __launch_bounds__(256) void prep_kernel(
    const float* __restrict__ q, const float* __restrict__ k,
    const float* __restrict__ qm, const float* __restrict__ km)
{
    int idx = blockIdx.x * 256 + threadIdx.x;      // pair index
    int dp = idx & 31;
    int l  = (idx >> 5) & 2047;
    int h  = (idx >> 16) & 7;
    int n  = idx >> 19;
    int srcp = (((n * 2048 + l) * 8 + h) << 5) + dp;

    float2 qv = ((const float2*)q)[srcp];
    float2 kv = ((const float2*)k)[srcp];
    float qmv = qm[n * 2048 + l];
    float kmv = km[n * 2048 + l];

    float phqx = ((qv.x > 0.f) ? (qv.x + 1.f) : __expf(qv.x)) * qmv;
    float phqy = ((qv.y > 0.f) ? (qv.y + 1.f) : __expf(qv.y)) * qmv;
    float phkx = ((kv.x > 0.f) ? (kv.x + 1.f) : __expf(kv.x)) * kmv;
    float phky = ((kv.y > 0.f) ? (kv.y + 1.f) : __expf(kv.y)) * kmv;

    __nv_bfloat16 qhx = __float2bfloat16(phqx), qhy = __float2bfloat16(phqy);
    __nv_bfloat16 khx = __float2bfloat16(phkx), khy = __float2bfloat16(phky);
    __nv_bfloat162 qh2; qh2.x = qhx; qh2.y = qhy;
    __nv_bfloat162 kh2; kh2.x = khx; kh2.y = khy;
    __nv_bfloat162 ql2; ql2.x = __float2bfloat16(phqx - __bfloat162float(qhx));
                        ql2.y = __float2bfloat16(phqy - __bfloat162float(qhy));
    __nv_bfloat162 kl2; kl2.x = __float2bfloat16(phkx - __bfloat162float(khx));
                        kl2.y = __float2bfloat16(phky - __bfloat162float(khy));

    ((__nv_bfloat162*)g_Qhi)[idx] = qh2;
    ((__nv_bfloat162*)g_Qlo)[idx] = ql2;
    ((__nv_bfloat162*)g_Khi)[idx] = kh2;
    ((__nv_bfloat162*)g_Klo)[idx] = kl2;
}

// ---------------------------------------------------------------------------
// Kernel B1: partial Ksum over s-chunks of 256.  grid = NHT*8
// ---------------------------------------------------------------------------
__global__ __launch_bounds__(256) void ksum_part_kernel()
{
    int nh = blockIdx.x >> 3;
    int ch = blockIdx.x & 7;
    int tid = threadIdx.x;
    int dp = tid & 31;
    int g  = tid >> 5;          // 0..7
    const uint32_t* bh = (const uint32_t*)(g_Khi + (size_t)nh * SK * DD) + (ch * 256) * 32;
    const uint32_t* bl = (const uint32_t*)(g_Klo + (size_t)nh * SK * DD) + (ch * 256) * 32;
    float s0 = 0.f, s1 = 0.f;
    for (int ss = g; ss < 256; ss += 8) {
        uint32_t vh = bh[ss * 32 + dp];
        uint32_t vl = bl[ss * 32 + dp];
        float2 fh = __bfloat1622float2(*(__nv_bfloat162*)&vh);
        float2 fl = __bfloat1622float2(*(__nv_bfloat162*)&vl);
        s0 += fh.x + fl.x;
        s1 += fh.y + fl.y;
    }
    __shared__ float r0[256], r1[256];
    r0[tid] = s0; r1[tid] = s1;
    __syncthreads();
    if (tid < 32) {
        float a0 = 0.f, a1 = 0.f;
        #pragma unroll
        for (int j = 0; j < 8; j++) { a0 += r0[tid + j * 32]; a1 += r1[tid + j * 32]; }
        g_kpart[(nh * 8 + ch) * 64 + tid * 2]     = a0;
        g_kpart[(nh * 8 + ch) * 64 + tid * 2 + 1] = a1;
    }
}

// Kernel B2: reduce partials.  grid = NHT, block = 64
__global__ __launch_bounds__(64) void ksum_final_kernel()
{
    int nh = blockIdx.x;
    int d = threadIdx.x;
    float s = 0.f;
    #pragma unroll
    for (int c = 0; c < 8; c++) s += g_kpart[(nh * 8 + c) * 64 + d];
    g_ksum[nh * 64 + d] = s;
}

// ---------------------------------------------------------------------------
// Kernel C: HMMA score GEMM (bf16 hi/lo 3-pass) + row-max + gate + output
// grid=(L/128, N*H), block=256 (8 warps 4x2), 2 CTAs/SM resident.
// ---------------------------------------------------------------------------
__global__ void __launch_bounds__(256, 2) attn_mma_kernel(
    const float* __restrict__ queries,
    const float* __restrict__ qmask,
    const float* __restrict__ W,
    const float* __restrict__ bias,
    float* __restrict__ out)
{
    extern __shared__ char sm[];
    const uint32_t smu = smem_u32_of(sm);
    float* rowmax = (float*)(sm + RMAX_OFF);
    float* ksum_s = (float*)(sm + KS_OFF);
    float* gate_s = (float*)(sm + GATE_OFF);

    const int tid  = threadIdx.x;
    const int lane = tid & 31;
    const int wid  = tid >> 5;
    const int wx   = wid & 1;       // n-block (64 cols)
    const int wy   = wid >> 1;      // m-block (32 rows)
    const int nh   = blockIdx.y;
    const int l0   = blockIdx.x * 128;

    // --- A tiles (Q hi/lo): LDG + swizzled STS, resident all kernel ---
    {
        const char* qh = (const char*)(g_Qhi + ((size_t)nh * LQ + l0) * DD);
        const char* ql = (const char*)(g_Qlo + ((size_t)nh * LQ + l0) * DD);
        #pragma unroll
        for (int c = tid; c < 1024; c += 256) {
            int row = c >> 3, dc = c & 7;
            uint32_t dst = row * 128 + ((dc ^ (row & 7)) << 4);
            *(uint4*)(sm + A_HI_OFF + dst) = *(const uint4*)(qh + c * 16);
            *(uint4*)(sm + A_LO_OFF + dst) = *(const uint4*)(ql + c * 16);
        }
    }
    if (tid < 64) ksum_s[tid] = g_ksum[nh * 64 + tid];

    const int mat    = lane >> 3;
    const int rin    = lane & 7;
    const int a_row  = wy * 32 + (mat & 1) * 8 + rin;
    const int a_kc   = mat >> 1;
    const int b_roff = wx * 64 + (mat >> 1) * 8 + rin;
    const int b_kc   = mat & 1;

    const char* khi_base = (const char*)(g_Khi + (size_t)nh * SK * DD);
    const char* klo_base = (const char*)(g_Klo + (size_t)nh * SK * DD);

    auto issue_b = [&](int buf, int t) {
        uint32_t bu = smu + B_OFF + buf * 32768;
        const char* gh = khi_base + (size_t)t * 128 * DD * 2;
        const char* gl = klo_base + (size_t)t * 128 * DD * 2;
        #pragma unroll
        for (int kk = 0; kk < 4; kk++) {
            int c = tid + kk * 256;
            int row = c >> 3, dc = c & 7;
            uint32_t sw = row * 128 + ((dc ^ (row & 7)) << 4);
            CPA16(bu + sw, gh + c * 16);
            CPA16(bu + 16384 + sw, gl + c * 16);
        }
    };

    issue_b(0, 0); CPC();

    float mA[2] = {-1e30f, -1e30f};
    float mB[2] = {-1e30f, -1e30f};

    for (int t = 0; t < 16; t++) {
        if (t < 15) { issue_b((t + 1) & 1, t + 1); CPC(); CPW1(); }
        else        { CPW0(); }
        __syncthreads();

        const uint32_t Bu = smu + B_OFF + (t & 1) * 32768;
        float acc[2][8][4];
        #pragma unroll
        for (int i = 0; i < 2; i++)
            #pragma unroll
            for (int j = 0; j < 8; j++)
                acc[i][j][0] = acc[i][j][1] = acc[i][j][2] = acc[i][j][3] = 0.f;

        #pragma unroll
        for (int ks = 0; ks < 4; ks++) {
            const int kb = ks * 2;
            uint32_t ah[2][4], al[2][4];
            #pragma unroll
            for (int i = 0; i < 2; i++) {
                int ar = a_row + 16 * i;
                uint32_t ad = smu + ar * 128 + (((a_kc + kb) ^ (ar & 7)) << 4);
                LDM4(ah[i], ad + A_HI_OFF);
                LDM4(al[i], ad + A_LO_OFF);
            }
            #pragma unroll
            for (int jp = 0; jp < 4; jp++) {
                int br = b_roff + jp * 16;
                uint32_t bd = Bu + br * 128 + (((b_kc + kb) ^ (br & 7)) << 4);
                uint32_t rh[4], rl[4];
                LDM4(rh, bd);
                LDM4(rl, bd + 16384);
                #pragma unroll
                for (int i = 0; i < 2; i++) {
                    MMA16816(acc[i][jp*2],   ah[i][0], ah[i][1], ah[i][2], ah[i][3], rh[0], rh[1]);
                    MMA16816(acc[i][jp*2],   ah[i][0], ah[i][1], ah[i][2], ah[i][3], rl[0], rl[1]);
                    MMA16816(acc[i][jp*2],   al[i][0], al[i][1], al[i][2], al[i][3], rh[0], rh[1]);
                    MMA16816(acc[i][jp*2+1], ah[i][0], ah[i][1], ah[i][2], ah[i][3], rh[2], rh[3]);
                    MMA16816(acc[i][jp*2+1], ah[i][0], ah[i][1], ah[i][2], ah[i][3], rl[2], rl[3]);
                    MMA16816(acc[i][jp*2+1], al[i][0], al[i][1], al[i][2], al[i][3], rh[2], rh[3]);
                }
            }
        }

        #pragma unroll
        for (int i = 0; i < 2; i++)
            #pragma unroll
            for (int j = 0; j < 8; j++) {
                mA[i] = fmaxf(mA[i], fmaxf(acc[i][j][0], acc[i][j][1]));
                mB[i] = fmaxf(mB[i], fmaxf(acc[i][j][2], acc[i][j][3]));
            }
        __syncthreads();
    }

    // --- reduce max across lane%4, write per-row per-wx ---
    #pragma unroll
    for (int off = 1; off <= 2; off <<= 1) {
        #pragma unroll
        for (int i = 0; i < 2; i++) {
            mA[i] = fmaxf(mA[i], __shfl_xor_sync(0xffffffff, mA[i], off));
            mB[i] = fmaxf(mB[i], __shfl_xor_sync(0xffffffff, mB[i], off));
        }
    }
    if ((lane & 3) == 0) {
        int r = lane >> 2;
        #pragma unroll
        for (int i = 0; i < 2; i++) {
            rowmax[(wy * 32 + i * 16 + r) * 2 + wx]     = mA[i];
            rowmax[(wy * 32 + i * 16 + r + 8) * 2 + wx] = mB[i];
        }
    }
    __syncthreads();

    // --- gate per row (tid<128), then all 256 threads write output ---
    if (tid < 128) {
        float mx = fmaxf(rowmax[tid * 2], rowmax[tid * 2 + 1]);
        float mean = 0.f;
        const int swl = tid & 7;
        #pragma unroll
        for (int dc = 0; dc < 8; dc++) {
            uint32_t off = tid * 128 + ((dc ^ swl) << 4);
            uint4 vh = *(const uint4*)(sm + A_HI_OFF + off);
            uint4 vl = *(const uint4*)(sm + A_LO_OFF + off);
            const uint32_t* ph = (const uint32_t*)&vh;
            const uint32_t* pl = (const uint32_t*)&vl;
            #pragma unroll
            for (int w = 0; w < 4; w++) {
                float2 fh = __bfloat1622float2(*(__nv_bfloat162*)&ph[w]);
                float2 fl = __bfloat1622float2(*(__nv_bfloat162*)&pl[w]);
                mean += (fh.x + fl.x) * ksum_s[dc * 8 + w * 2];
                mean += (fh.y + fl.y) * ksum_s[dc * 8 + w * 2 + 1];
            }
        }
        mean *= (1.0f / (float)SK);
        float lg = fmaf(mean, W[0], fmaf(mx, W[1], bias[0]));
        float gate = 1.0f / (1.0f + __expf(-lg));
        const int n = nh >> 3;
        gate_s[tid] = gate * qmask[n * LQ + l0 + tid];
    }
    __syncthreads();

    {
        const int n = nh >> 3;
        const int h = nh & 7;
        const int lrow = tid >> 1;
        const int half = tid & 1;
        const int l = l0 + lrow;
        float s = gate_s[lrow];
        size_t obase = ((((size_t)n * LQ + l) * HH + h) << 6) + half * 32;
        const float4* qs = (const float4*)(queries + obase);
        float4* dst = (float4*)(out + obase);
        #pragma unroll
        for (int j = 0; j < 8; j++) {
            float4 v = qs[j];
            v.x *= s; v.y *= s; v.z *= s; v.w *= s;
            dst[j] = v;
        }
    }
}

// ---------------------------------------------------------------------------
extern "C" void kernel_launch(void* const* d_in, const int* in_sizes, int n_in,
                              void* d_out, int out_size)
{
    const float* queries = (const float*)d_in[0];
    const float* keys    = (const float*)d_in[1];
    const float* q_mask  = (const float*)d_in[3];
    const float* kv_mask = (const float*)d_in[4];
    const float* W       = (const float*)d_in[5];
    const float* b       = (const float*)d_in[6];
    float* out = (float*)d_out;

    prep_kernel<<<(NHLD / 2) / 256, 256>>>(queries, keys, q_mask, kv_mask);
    ksum_part_kernel<<<NHT * 8, 256>>>();
    ksum_final_kernel<<<NHT, 64>>>();

    cudaFuncSetAttribute(attn_mma_kernel,
                         cudaFuncAttributeMaxDynamicSharedMemorySize, SMEM_TOTAL);
    dim3 grid(LQ / 128, NHT);
    attn_mma_kernel<<<grid, 256, SMEM_TOTAL>>>(queries, q_mask, W, b, out);
}